// round 15
// baseline (speedup 1.0000x reference)
#include <cuda_runtime.h>

// R15 = R14 logic at wider geometry: GRID=128, T=512, E=1 -> 4 warps/SMSP on
// 128 SMs (was 8 on 32). Issue-bound model: per-warp A cost is T-invariant,
// so halving warps/SMSP halves A-phase time. R12's regressions NOT carried:
// tid0-only fences, no dp4a counting. Resolve = R12-verified 4-blocks-per-lane
// scan on transposed counts (coalesced). Two-flag overlap kept from R14.

#define NSUBJ 1024
#define T 512
#define NWARP 16          // warps per block
#define GRID 128
#define MAXP 50
#define CAP 51
#define NLOSS 4

#define WCNT_B (NWARP * NSUBJ * 4)       // 65536 (u32, [warp][subject])
#define SMEM_TOTAL (WCNT_B + 4096 /*scnt*/ + 2*MAXP*4*2 + 16 + 128 + 64)

__device__ volatile unsigned g_flagCnt[GRID];   // per-block counts published
__device__ volatile unsigned g_flagScat[GRID];  // scatter published
__device__ volatile unsigned g_flagL[NLOSS];    // loss partial published
__device__ float g_part[NLOSS];
__device__ unsigned short g_bcntT[NSUBJ * GRID];        // [subject][block] transposed
__device__ unsigned short g_lidx[GRID * NSUBJ * CAP];   // [block][subject][slot] local idx

// subject_ids may be int64 or (jax x64-off) int32: one broadcast load + vote.
__device__ __forceinline__ bool detect64(const void* p, int lane) {
    long long v = ((const long long*)p)[lane & 15];
    bool ok = (v >= 0 && v < (long long)NSUBJ);
    return __all_sync(0xFFFFFFFFu, ok);
}

// Warp-cooperative: (subject, global slot) -> global element index.
// Lane l owns blocks 4l..4l+3 (contiguous ushort4 row: coalesced 256B/warp).
__device__ __forceinline__ int resolve_idx(int s, int slot, int lane) {
    const ushort4 c4 = *(const ushort4*)(&g_bcntT[s * GRID + 4 * lane]);
    int c[4] = {(int)c4.x, (int)c4.y, (int)c4.z, (int)c4.w};
    int lt = c[0] + c[1] + c[2] + c[3];
    int sc = lt;
#pragma unroll
    for (int d = 1; d < 32; d <<= 1) {
        int t = __shfl_up_sync(0xFFFFFFFFu, sc, d);
        if (lane >= d) sc += t;
    }
    int off = sc - lt;                    // exclusive offset of block 4*lane
    int blk = -1, loc = 0;
#pragma unroll
    for (int r = 0; r < 4; r++) {
        if (slot >= off && slot < off + c[r]) { blk = 4 * lane + r; loc = slot - off; }
        off += c[r];
    }
    int idx = 0;
    if (blk >= 0) idx = blk * T + (int)g_lidx[(blk * NSUBJ + s) * CAP + loc];
    unsigned m = __ballot_sync(0xFFFFFFFFu, blk >= 0);
    return __shfl_sync(0xFFFFFFFFu, idx, __ffs(m) - 1);
}

__global__ void __launch_bounds__(T, 1)
fused_contrastive(const void* __restrict__ sids, const float* __restrict__ x,
                  float* __restrict__ out, int B, int D) {
    extern __shared__ unsigned char sm[];
    unsigned* wc = (unsigned*)sm;                   // [warp*NSUBJ + s] u32
    int* scnt = (int*)(sm + WCNT_B);                // [s] totals (loss blocks)
    int* ii   = scnt + NSUBJ;                       // encoded s*CAP+slot
    int* jj   = ii + 2 * MAXP;
    int* npn  = jj + 2 * MAXP;
    float* part = (float*)(npn + 4);                // [NWARP]

    const int tid = threadIdx.x, lane = tid & 31, w = tid >> 5;
    const int b = blockIdx.x;
    const bool is64 = detect64(sids, lane);
    const unsigned epoch = g_flagCnt[b] + 1u;       // own flag: replay-safe

    const int i = b * T + tid;                      // one element per thread

    // zero wc: 16384 words / 512 threads = 32 each (conflict-free stride)
    for (int k = tid; k < NWARP * NSUBJ; k += T) wc[k] = 0u;
    __syncthreads();

    // ---- A1: single sid load; per-(subject,warp) counts ----
    const bool valid = i < B;
    long long v = 0;
    if (valid) v = is64 ? ((const long long*)sids)[i] : (long long)((const int*)sids)[i];
    const int s = valid ? (int)v : 0;
    const int key = valid ? s : (NSUBJ + lane);
    const unsigned mask = __match_any_sync(0xFFFFFFFFu, key);
    const int rank = __popc(mask & ((1u << lane) - 1u));
    if (valid && lane == (__ffs(mask) - 1))
        wc[w * NSUBJ + s] += __popc(mask);
    __syncthreads();

    // ---- A2: block-local exclusive prefix over 16 warps (2 subjects/thread);
    //      publish per-block count TRANSPOSED, then flagCnt ----
#pragma unroll
    for (int r = 0; r < NSUBJ / T; r++) {
        int s2 = tid + r * T;
        int run = 0;
#pragma unroll
        for (int c = 0; c < NWARP; c++) {
            int u = (int)wc[c * NSUBJ + s2];
            wc[c * NSUBJ + s2] = (unsigned)run;
            run += u;
        }
        g_bcntT[s2 * GRID + b] = (unsigned short)run;
    }
    __syncthreads();
    if (tid == 0) {
        __threadfence();
        g_flagCnt[b] = epoch;
    }

    // ---- A3: block-LOCAL order-preserving scatter ----
    if (valid) {
        int cur = (int)wc[w * NSUBJ + s];           // all lanes read before leader store
        int slot = cur + rank;                      // LOCAL ordered slot
        if (lane == (__ffs(mask) - 1))
            wc[w * NSUBJ + s] = (unsigned)(cur + __popc(mask));
        if (slot < CAP)
            g_lidx[(b * NSUBJ + s) * CAP + slot] = (unsigned short)tid;
    }
    __syncthreads();

    // ---- publish scatter; non-loss blocks exit ----
    if (tid == 0) {
        __threadfence();
        g_flagScat[b] = epoch;
    }
    if (b >= NLOSS) return;

    // ---- wait for all COUNTS (overlaps others' scatter) ----
    for (int t = tid; t < GRID; t += T)
        while (g_flagCnt[t] < epoch) { }
    __syncthreads();
    __threadfence();

    // ---- B: per-subject totals; carry-safe unpack of packed u16 rows ----
#pragma unroll
    for (int r = 0; r < NSUBJ / T; r++) {
        int s2 = tid + r * T;
        const unsigned* row = (const unsigned*)(&g_bcntT[s2 * GRID]);
        int tot = 0;
#pragma unroll 16
        for (int c = 0; c < GRID / 2; c++) {
            unsigned u = row[c];
            tot += (int)(u & 0xFFFFu) + (int)(u >> 16);
        }
        scnt[s2] = tot;
    }
    __syncthreads();

    // ---- D1: exact reference pair enumeration (pos: tid 0, neg: tid 32) ----
    if (tid == 0) {                                  // positive pairs
        int npos = 0;
        for (int ss = 0; ss < NSUBJ && npos < MAXP; ss++) {
            int cs = scnt[ss];
            if (cs < 2) continue;
            int til = cs < CAP ? cs : CAP;
            for (int a = 0; a < til && npos < MAXP; a++)
                for (int bb = a + 1; bb < til && npos < MAXP; bb++) {
                    ii[npos] = ss * CAP + a;
                    jj[npos] = ss * CAP + bb;
                    npos++;
                }
        }
        npn[0] = npos;
    }
    if (tid == 32) {                                 // negative pairs
        int nneg = 0;
        for (int ss = 0; ss < NSUBJ && nneg < MAXP; ss++) {
            int cs = scnt[ss];
            if (cs == 0) continue;
            int til = cs < CAP ? cs : CAP;
            for (int o = 0; o < NSUBJ; o++) {
                int co = scnt[o];
                if (co == 0) continue;
                if (o == ss) continue;               // python: continue precedes break
                if (nneg >= MAXP) break;
                int tjl = co < CAP ? co : CAP;
                for (int a = 0; a < til && nneg < MAXP; a++)
                    for (int bb = 0; bb < tjl && nneg < MAXP; bb++) {
                        ii[MAXP + nneg] = ss * CAP + a;
                        jj[MAXP + nneg] = o * CAP + bb;
                        nneg++;
                    }
            }
        }
        npn[1] = nneg;
    }

    // ---- wait for all SCATTERS (g_lidx reads below need them) ----
    for (int t = tid; t < GRID; t += T)
        while (g_flagScat[t] < epoch) { }
    __syncthreads();
    __threadfence();

    // ---- D2: warp per pair (p % NLOSS == b); lazy resolve + loss ----
    const int npos = npn[0], nneg = npn[1], n = npos + nneg;
    float acc = 0.0f;
    const int nvec = D / 4;                          // D=384 -> 96 float4
    for (int p = b + NLOSS * w; p < n; p += NLOSS * NWARP) {
        int slot = (p < npos) ? p : (MAXP + (p - npos));
        int hi = ii[slot], hj = jj[slot];
        int ei = resolve_idx(hi / CAP, hi % CAP, lane);
        int ej = resolve_idx(hj / CAP, hj % CAP, lane);
        const float4* xi = (const float4*)(x + (long long)ei * D);
        const float4* xj = (const float4*)(x + (long long)ej * D);
        float sxx = 0.f, syy = 0.f, sxy = 0.f;
        for (int q = lane; q < nvec; q += 32) {
            float4 a = xi[q];
            float4 bq = xj[q];
            sxx += a.x * a.x + a.y * a.y + a.z * a.z + a.w * a.w;
            syy += bq.x * bq.x + bq.y * bq.y + bq.z * bq.z + bq.w * bq.w;
            sxy += a.x * bq.x + a.y * bq.y + a.z * bq.z + a.w * bq.w;
        }
#pragma unroll
        for (int o = 16; o; o >>= 1) {
            sxx += __shfl_xor_sync(0xFFFFFFFFu, sxx, o);
            syy += __shfl_xor_sync(0xFFFFFFFFu, syy, o);
            sxy += __shfl_xor_sync(0xFFFFFFFFu, sxy, o);
        }
        float ni = fmaxf(sqrtf(sxx), 1e-12f);
        float nj = fmaxf(sqrtf(syy), 1e-12f);
        float sc = (sxy / (ni * nj)) * 2.0f;         // / TEMPERATURE (0.5)
        float xs = (p < npos) ? -sc : sc;
        acc += fmaxf(xs, 0.f) + log1pf(expf(-fabsf(xs)));  // softplus(xs)
    }

    // acc replicated across lanes -> lane 0's copy IS the warp partial
    if (lane == 0) part[w] = acc;
    __syncthreads();
    if (w == 0) {
        float vv = (lane < NWARP) ? part[lane] : 0.0f;
#pragma unroll
        for (int o = 16; o; o >>= 1) vv += __shfl_xor_sync(0xFFFFFFFFu, vv, o);
        if (lane == 0) {
            g_part[b] = vv;
            __threadfence();
            g_flagL[b] = epoch;
        }
    }

    // ---- block 0 combines the NLOSS partials deterministically ----
    if (b == 0) {
        if (tid < NLOSS)
            while (g_flagL[tid] < epoch) { }
        __syncthreads();
        __threadfence();
        if (tid == 0) {
            float tot = 0.0f;
#pragma unroll
            for (int r = 0; r < NLOSS; r++) tot += g_part[r];
            out[0] = tot / (float)n;
        }
    }
}

extern "C" void kernel_launch(void* const* d_in, const int* in_sizes, int n_in,
                              void* d_out, int out_size) {
    const float* x = (const float*)d_in[0];   // identity_tokens [B, D] fp32
    const void* sids = d_in[1];               // subject_ids [B]
    int B = in_sizes[1];
    int D = in_sizes[0] / B;

    cudaFuncSetAttribute(fused_contrastive,
                         cudaFuncAttributeMaxDynamicSharedMemorySize, SMEM_TOTAL);

    fused_contrastive<<<GRID, T, SMEM_TOTAL>>>(sids, x, (float*)d_out, B, D);
}

// round 16
// speedup vs baseline: 1.9796x; 1.9796x over previous
#include <cuda_runtime.h>

// R16 = R14 verified design (T=1024, u32 transposed wc, two-flag overlap,
// tid0 publish, split enumeration, lazy resolve, NLOSS=4 deterministic
// combine) moved one more step along the only reliably-positive axis:
// GRID 32 -> 16 (E=4). T=512 geometries are empirically forbidden (R12, R15).

#define NSUBJ 1024
#define T 1024
#define NWARP 32
#define GRID 16
#define E 4
#define ET (E * T)        // 4096 elements per block
#define MAXP 50
#define CAP 51
#define NLOSS 4

#define WCNT_B (NWARP * NSUBJ * 4)       // 131072 (u32, [warp][subject])
#define SMEM_TOTAL (WCNT_B + 4096 /*scnt*/ + 2*MAXP*4*2 + 16 + 128 + 64)

__device__ volatile unsigned g_flagCnt[GRID];   // per-block counts published
__device__ volatile unsigned g_flagScat[GRID];  // scatter published
__device__ volatile unsigned g_flagL[NLOSS];    // loss partial published
__device__ float g_part[NLOSS];
__device__ unsigned short g_bcntT[NSUBJ * GRID];        // [subject][block] transposed
__device__ unsigned short g_lidx[GRID * NSUBJ * CAP];   // [block][subject][slot] local idx

// subject_ids may be int64 or (jax x64-off) int32: one broadcast load + vote.
__device__ __forceinline__ bool detect64(const void* p, int lane) {
    long long v = ((const long long*)p)[lane & 15];
    bool ok = (v >= 0 && v < (long long)NSUBJ);
    return __all_sync(0xFFFFFFFFu, ok);
}

__device__ __forceinline__ long long sid_or_neg(const void* p, int i, int B, bool is64) {
    if (i >= B) return -1ll;
    return is64 ? ((const long long*)p)[i] : (long long)((const int*)p)[i];
}

// Warp-cooperative: (subject, global slot) -> global element index.
// Lanes 0..15 hold the 16 per-block counts (32B row); 5-step shfl scan.
__device__ __forceinline__ int resolve_idx(int s, int slot, int lane) {
    int u = (lane < GRID) ? (int)g_bcntT[s * GRID + lane] : 0;
    int sc = u;
#pragma unroll
    for (int d = 1; d < 32; d <<= 1) {
        int t = __shfl_up_sync(0xFFFFFFFFu, sc, d);
        if (lane >= d) sc += t;
    }
    int e0 = sc - u;                                // exclusive offset of block `lane`
    bool hit = (lane < GRID) && (slot >= e0) && (slot < e0 + u);
    int idx = 0;
    if (hit)
        idx = lane * ET + (int)g_lidx[(lane * NSUBJ + s) * CAP + (slot - e0)];
    unsigned m = __ballot_sync(0xFFFFFFFFu, hit);
    return __shfl_sync(0xFFFFFFFFu, idx, __ffs(m) - 1);
}

__global__ void __launch_bounds__(T, 1)
fused_contrastive(const void* __restrict__ sids, const float* __restrict__ x,
                  float* __restrict__ out, int B, int D) {
    extern __shared__ unsigned char sm[];
    unsigned* wc = (unsigned*)sm;                   // [warp*NSUBJ + s] u32
    int* scnt = (int*)(sm + WCNT_B);                // [s] totals (loss blocks)
    int* ii   = scnt + NSUBJ;                       // encoded s*CAP+slot
    int* jj   = ii + 2 * MAXP;
    int* npn  = jj + 2 * MAXP;
    float* part = (float*)(npn + 4);                // [32]

    const int tid = threadIdx.x, lane = tid & 31, w = tid >> 5;
    const int b = blockIdx.x;
    const bool is64 = detect64(sids, lane);
    const unsigned epoch = g_flagCnt[b] + 1u;       // own flag: replay-safe

    const int base = b * ET + w * (E * 32);         // warp-contiguous range

    // zero wc (consecutive words per thread: conflict-free)
    for (int k = tid; k < NWARP * NSUBJ; k += T) wc[k] = 0u;
    __syncthreads();

    // ---- A1: per-(subject,warp) counts, E rounds; retain sids in regs ----
    long long vr[E];
#pragma unroll
    for (int k = 0; k < E; k++)
        vr[k] = sid_or_neg(sids, base + k * 32 + lane, B, is64);
#pragma unroll
    for (int k = 0; k < E; k++) {
        bool valid = vr[k] >= 0;
        int s = valid ? (int)vr[k] : 0;
        int key = valid ? s : (NSUBJ + lane);
        unsigned mask = __match_any_sync(0xFFFFFFFFu, key);
        if (valid && lane == (__ffs(mask) - 1))
            wc[w * NSUBJ + s] += __popc(mask);
    }
    __syncthreads();

    // ---- A2: block-local exclusive prefix over warps (conflict-free scan);
    //      publish per-block count TRANSPOSED, then flagCnt ----
    {
        int s = tid;
        int run = 0;
#pragma unroll
        for (int c = 0; c < NWARP; c++) {
            int v = (int)wc[c * NSUBJ + s];
            wc[c * NSUBJ + s] = (unsigned)run;
            run += v;
        }
        g_bcntT[s * GRID + b] = (unsigned short)run;
    }
    __syncthreads();
    if (tid == 0) {
        __threadfence();
        g_flagCnt[b] = epoch;
    }

    // ---- A3: block-LOCAL order-preserving scatter, E rounds ----
#pragma unroll
    for (int k = 0; k < E; k++) {
        int i = base + k * 32 + lane;
        bool valid = vr[k] >= 0;
        int s = valid ? (int)vr[k] : 0;
        int key = valid ? s : (NSUBJ + lane);
        unsigned mask = __match_any_sync(0xFFFFFFFFu, key);
        if (valid) {
            int rank = __popc(mask & ((1u << lane) - 1u));
            int cur = (int)wc[w * NSUBJ + s];       // all lanes read before leader store
            int slot = cur + rank;                  // LOCAL slot
            if (lane == (__ffs(mask) - 1))
                wc[w * NSUBJ + s] = (unsigned)(cur + __popc(mask));
            if (slot < CAP)
                g_lidx[(b * NSUBJ + s) * CAP + slot] = (unsigned short)(i - b * ET);
        }
    }
    __syncthreads();

    // ---- publish scatter; non-loss blocks exit ----
    if (tid == 0) {
        __threadfence();
        g_flagScat[b] = epoch;
    }
    if (b >= NLOSS) return;

    // ---- wait for all COUNTS (overlaps others' scatter) ----
    for (int t = tid; t < GRID; t += T)
        while (g_flagCnt[t] < epoch) { }
    __syncthreads();
    __threadfence();

    // ---- B: per-subject totals; 32B row per subject, carry-safe unpack ----
    {
        const unsigned* row = (const unsigned*)(&g_bcntT[tid * GRID]);
        int tot = 0;
#pragma unroll
        for (int c = 0; c < GRID / 2; c++) {
            unsigned u = row[c];
            tot += (int)(u & 0xFFFFu) + (int)(u >> 16);
        }
        scnt[tid] = tot;
    }
    __syncthreads();

    // ---- D1: exact reference pair enumeration (pos: tid 0, neg: tid 32;
    //      independent given scnt). Handles: s*CAP + global_slot. ----
    if (tid == 0) {                                  // positive pairs
        int npos = 0;
        for (int ss = 0; ss < NSUBJ && npos < MAXP; ss++) {
            int cs = scnt[ss];
            if (cs < 2) continue;
            int til = cs < CAP ? cs : CAP;
            for (int a = 0; a < til && npos < MAXP; a++)
                for (int bb = a + 1; bb < til && npos < MAXP; bb++) {
                    ii[npos] = ss * CAP + a;
                    jj[npos] = ss * CAP + bb;
                    npos++;
                }
        }
        npn[0] = npos;
    }
    if (tid == 32) {                                 // negative pairs
        int nneg = 0;
        for (int ss = 0; ss < NSUBJ && nneg < MAXP; ss++) {
            int cs = scnt[ss];
            if (cs == 0) continue;
            int til = cs < CAP ? cs : CAP;
            for (int o = 0; o < NSUBJ; o++) {
                int co = scnt[o];
                if (co == 0) continue;
                if (o == ss) continue;               // python: continue precedes break
                if (nneg >= MAXP) break;
                int tjl = co < CAP ? co : CAP;
                for (int a = 0; a < til && nneg < MAXP; a++)
                    for (int bb = 0; bb < tjl && nneg < MAXP; bb++) {
                        ii[MAXP + nneg] = ss * CAP + a;
                        jj[MAXP + nneg] = o * CAP + bb;
                        nneg++;
                    }
            }
        }
        npn[1] = nneg;
    }

    // ---- wait for all SCATTERS (g_lidx reads below need them) ----
    for (int t = tid; t < GRID; t += T)
        while (g_flagScat[t] < epoch) { }
    __syncthreads();
    __threadfence();

    // ---- D2: warp per pair (p % NLOSS == b); lazy resolve + loss ----
    const int npos = npn[0], nneg = npn[1], n = npos + nneg;
    float acc = 0.0f;
    const int nvec = D / 4;                          // D=384 -> 96 float4
    for (int p = b + NLOSS * w; p < n; p += NLOSS * NWARP) {
        int slot = (p < npos) ? p : (MAXP + (p - npos));
        int hi = ii[slot], hj = jj[slot];
        int ei = resolve_idx(hi / CAP, hi % CAP, lane);
        int ej = resolve_idx(hj / CAP, hj % CAP, lane);
        const float4* xi = (const float4*)(x + (long long)ei * D);
        const float4* xj = (const float4*)(x + (long long)ej * D);
        float sxx = 0.f, syy = 0.f, sxy = 0.f;
        for (int q = lane; q < nvec; q += 32) {
            float4 a = xi[q];
            float4 bq = xj[q];
            sxx += a.x * a.x + a.y * a.y + a.z * a.z + a.w * a.w;
            syy += bq.x * bq.x + bq.y * bq.y + bq.z * bq.z + bq.w * bq.w;
            sxy += a.x * bq.x + a.y * bq.y + a.z * bq.z + a.w * bq.w;
        }
#pragma unroll
        for (int o = 16; o; o >>= 1) {
            sxx += __shfl_xor_sync(0xFFFFFFFFu, sxx, o);
            syy += __shfl_xor_sync(0xFFFFFFFFu, syy, o);
            sxy += __shfl_xor_sync(0xFFFFFFFFu, sxy, o);
        }
        float ni = fmaxf(sqrtf(sxx), 1e-12f);
        float nj = fmaxf(sqrtf(syy), 1e-12f);
        float sc = (sxy / (ni * nj)) * 2.0f;         // / TEMPERATURE (0.5)
        float xs = (p < npos) ? -sc : sc;
        acc += fmaxf(xs, 0.f) + log1pf(expf(-fabsf(xs)));  // softplus(xs)
    }

    // acc replicated across lanes -> lane 0's copy IS the warp partial
    if (lane == 0) part[w] = acc;
    __syncthreads();
    if (w == 0) {
        float vv = part[lane];
#pragma unroll
        for (int o = 16; o; o >>= 1) vv += __shfl_xor_sync(0xFFFFFFFFu, vv, o);
        if (lane == 0) {
            g_part[b] = vv;
            __threadfence();
            g_flagL[b] = epoch;
        }
    }

    // ---- block 0 combines the NLOSS partials deterministically ----
    if (b == 0) {
        if (tid < NLOSS)
            while (g_flagL[tid] < epoch) { }
        __syncthreads();
        __threadfence();
        if (tid == 0) {
            float tot = 0.0f;
#pragma unroll
            for (int r = 0; r < NLOSS; r++) tot += g_part[r];
            out[0] = tot / (float)n;
        }
    }
}

extern "C" void kernel_launch(void* const* d_in, const int* in_sizes, int n_in,
                              void* d_out, int out_size) {
    const float* x = (const float*)d_in[0];   // identity_tokens [B, D] fp32
    const void* sids = d_in[1];               // subject_ids [B]
    int B = in_sizes[1];
    int D = in_sizes[0] / B;

    cudaFuncSetAttribute(fused_contrastive,
                         cudaFuncAttributeMaxDynamicSharedMemorySize, SMEM_TOTAL);

    fused_contrastive<<<GRID, T, SMEM_TOTAL>>>(sids, x, (float*)d_out, B, D);
}

// round 17
// speedup vs baseline: 2.1556x; 1.0889x over previous
#include <cuda_runtime.h>

// R17 = R14 (the 18.9us converged design: T=1024, GRID=32, E=2, u32 transposed
// wc, two-flag overlap, tid0 publish, split enumeration, lazy resolve, NLOSS=4
// deterministic combine) + two zero-risk micro-trims:
//  (a) sid LDG.64s hoisted ABOVE the wc zero loop (DRAM latency overlaps it)
//  (b) wc zeroed with uint4 stores (8x STS.128 vs 32x STS.32 per thread)
// Geometry sweep closed: GRID 64/32/16 -> 20.4/18.9/24.1; T=512 forbidden.

#define NSUBJ 1024
#define T 1024
#define NWARP 32
#define GRID 32
#define E 2
#define ET (E * T)        // 2048 elements per block
#define MAXP 50
#define CAP 51
#define NLOSS 4

#define WCNT_B (NWARP * NSUBJ * 4)       // 131072 (u32, [warp][subject])
#define SMEM_TOTAL (WCNT_B + 4096 /*scnt*/ + 2*MAXP*4*2 + 16 + 128 + 64)

__device__ volatile unsigned g_flagCnt[GRID];   // per-block counts published
__device__ volatile unsigned g_flagScat[GRID];  // scatter published
__device__ volatile unsigned g_flagL[NLOSS];    // loss partial published
__device__ float g_part[NLOSS];
__device__ unsigned short g_bcntT[NSUBJ * GRID];        // [subject][block] transposed
__device__ unsigned short g_lidx[GRID * NSUBJ * CAP];   // [block][subject][slot] local idx

// subject_ids may be int64 or (jax x64-off) int32: one broadcast load + vote.
__device__ __forceinline__ bool detect64(const void* p, int lane) {
    long long v = ((const long long*)p)[lane & 15];
    bool ok = (v >= 0 && v < (long long)NSUBJ);
    return __all_sync(0xFFFFFFFFu, ok);
}

__device__ __forceinline__ long long sid_or_neg(const void* p, int i, int B, bool is64) {
    if (i >= B) return -1ll;
    return is64 ? ((const long long*)p)[i] : (long long)((const int*)p)[i];
}

// Warp-cooperative: (subject, global slot) -> global element index.
// One coalesced 64B u16 row (g_bcntT[s][0..31]), 5-step shfl scan.
__device__ __forceinline__ int resolve_idx(int s, int slot, int lane) {
    int u = (int)g_bcntT[s * GRID + lane];          // coalesced u16 row
    int sc = u;
#pragma unroll
    for (int d = 1; d < 32; d <<= 1) {
        int t = __shfl_up_sync(0xFFFFFFFFu, sc, d);
        if (lane >= d) sc += t;
    }
    int e0 = sc - u;                                // exclusive offset of block `lane`
    bool hit = (slot >= e0) && (slot < e0 + u);
    int idx = 0;
    if (hit)
        idx = lane * ET + (int)g_lidx[(lane * NSUBJ + s) * CAP + (slot - e0)];
    unsigned m = __ballot_sync(0xFFFFFFFFu, hit);
    return __shfl_sync(0xFFFFFFFFu, idx, __ffs(m) - 1);
}

__global__ void __launch_bounds__(T, 1)
fused_contrastive(const void* __restrict__ sids, const float* __restrict__ x,
                  float* __restrict__ out, int B, int D) {
    extern __shared__ unsigned char sm[];
    unsigned* wc = (unsigned*)sm;                   // [warp*NSUBJ + s] u32
    int* scnt = (int*)(sm + WCNT_B);                // [s] totals (loss blocks)
    int* ii   = scnt + NSUBJ;                       // encoded s*CAP+slot
    int* jj   = ii + 2 * MAXP;
    int* npn  = jj + 2 * MAXP;
    float* part = (float*)(npn + 4);                // [32]

    const int tid = threadIdx.x, lane = tid & 31, w = tid >> 5;
    const int b = blockIdx.x;
    const bool is64 = detect64(sids, lane);
    const unsigned epoch = g_flagCnt[b] + 1u;       // own flag: replay-safe

    const int base = b * ET + w * (E * 32);         // warp-contiguous range

    // (a) hoist the only cold global loads: their latency overlaps the zero loop
    long long vr[E];
#pragma unroll
    for (int k = 0; k < E; k++)
        vr[k] = sid_or_neg(sids, base + k * 32 + lane, B, is64);

    // (b) zero wc with 128-bit stores: 8 iterations/thread
    {
        uint4* z = (uint4*)wc;
        const uint4 z0 = make_uint4(0u, 0u, 0u, 0u);
#pragma unroll
        for (int k = 0; k < (NWARP * NSUBJ / 4) / T; k++)
            z[tid + k * T] = z0;
    }
    __syncthreads();

    // ---- A1: per-(subject,warp) counts, E rounds (sids already in regs) ----
#pragma unroll
    for (int k = 0; k < E; k++) {
        bool valid = vr[k] >= 0;
        int s = valid ? (int)vr[k] : 0;
        int key = valid ? s : (NSUBJ + lane);
        unsigned mask = __match_any_sync(0xFFFFFFFFu, key);
        if (valid && lane == (__ffs(mask) - 1))
            wc[w * NSUBJ + s] += __popc(mask);
    }
    __syncthreads();

    // ---- A2: block-local exclusive prefix over warps (conflict-free scan);
    //      publish per-block count TRANSPOSED, then flagCnt ----
    {
        int s = tid;
        int run = 0;
#pragma unroll
        for (int c = 0; c < NWARP; c++) {
            int v = (int)wc[c * NSUBJ + s];
            wc[c * NSUBJ + s] = (unsigned)run;
            run += v;
        }
        g_bcntT[s * GRID + b] = (unsigned short)run;
    }
    __syncthreads();
    if (tid == 0) {
        __threadfence();
        g_flagCnt[b] = epoch;
    }

    // ---- A3: block-LOCAL order-preserving scatter, E rounds ----
#pragma unroll
    for (int k = 0; k < E; k++) {
        int i = base + k * 32 + lane;
        bool valid = vr[k] >= 0;
        int s = valid ? (int)vr[k] : 0;
        int key = valid ? s : (NSUBJ + lane);
        unsigned mask = __match_any_sync(0xFFFFFFFFu, key);
        if (valid) {
            int rank = __popc(mask & ((1u << lane) - 1u));
            int cur = (int)wc[w * NSUBJ + s];       // all lanes read before leader store
            int slot = cur + rank;                  // LOCAL slot
            if (lane == (__ffs(mask) - 1))
                wc[w * NSUBJ + s] = (unsigned)(cur + __popc(mask));
            if (slot < CAP)
                g_lidx[(b * NSUBJ + s) * CAP + slot] = (unsigned short)(i - b * ET);
        }
    }
    __syncthreads();

    // ---- publish scatter; non-loss blocks exit ----
    if (tid == 0) {
        __threadfence();
        g_flagScat[b] = epoch;
    }
    if (b >= NLOSS) return;

    // ---- wait for all COUNTS (overlaps others' scatter) ----
    for (int t = tid; t < GRID; t += T)
        while (g_flagCnt[t] < epoch) { }
    __syncthreads();
    __threadfence();

    // ---- B: per-subject totals; 64B row per subject, carry-safe unpack ----
    {
        const unsigned* row = (const unsigned*)(&g_bcntT[tid * GRID]);
        int tot = 0;
#pragma unroll
        for (int c = 0; c < GRID / 2; c++) {
            unsigned u = row[c];
            tot += (int)(u & 0xFFFFu) + (int)(u >> 16);
        }
        scnt[tid] = tot;
    }
    __syncthreads();

    // ---- D1: exact reference pair enumeration (pos: tid 0, neg: tid 32;
    //      independent given scnt). Handles: s*CAP + global_slot. ----
    if (tid == 0) {                                  // positive pairs
        int npos = 0;
        for (int ss = 0; ss < NSUBJ && npos < MAXP; ss++) {
            int cs = scnt[ss];
            if (cs < 2) continue;
            int til = cs < CAP ? cs : CAP;
            for (int a = 0; a < til && npos < MAXP; a++)
                for (int bb = a + 1; bb < til && npos < MAXP; bb++) {
                    ii[npos] = ss * CAP + a;
                    jj[npos] = ss * CAP + bb;
                    npos++;
                }
        }
        npn[0] = npos;
    }
    if (tid == 32) {                                 // negative pairs
        int nneg = 0;
        for (int ss = 0; ss < NSUBJ && nneg < MAXP; ss++) {
            int cs = scnt[ss];
            if (cs == 0) continue;
            int til = cs < CAP ? cs : CAP;
            for (int o = 0; o < NSUBJ; o++) {
                int co = scnt[o];
                if (co == 0) continue;
                if (o == ss) continue;               // python: continue precedes break
                if (nneg >= MAXP) break;
                int tjl = co < CAP ? co : CAP;
                for (int a = 0; a < til && nneg < MAXP; a++)
                    for (int bb = 0; bb < tjl && nneg < MAXP; bb++) {
                        ii[MAXP + nneg] = ss * CAP + a;
                        jj[MAXP + nneg] = o * CAP + bb;
                        nneg++;
                    }
            }
        }
        npn[1] = nneg;
    }

    // ---- wait for all SCATTERS (g_lidx reads below need them) ----
    for (int t = tid; t < GRID; t += T)
        while (g_flagScat[t] < epoch) { }
    __syncthreads();
    __threadfence();

    // ---- D2: warp per pair (p % NLOSS == b); lazy resolve + loss ----
    const int npos = npn[0], nneg = npn[1], n = npos + nneg;
    float acc = 0.0f;
    const int nvec = D / 4;                          // D=384 -> 96 float4
    for (int p = b + NLOSS * w; p < n; p += NLOSS * NWARP) {
        int slot = (p < npos) ? p : (MAXP + (p - npos));
        int hi = ii[slot], hj = jj[slot];
        int ei = resolve_idx(hi / CAP, hi % CAP, lane);
        int ej = resolve_idx(hj / CAP, hj % CAP, lane);
        const float4* xi = (const float4*)(x + (long long)ei * D);
        const float4* xj = (const float4*)(x + (long long)ej * D);
        float sxx = 0.f, syy = 0.f, sxy = 0.f;
        for (int q = lane; q < nvec; q += 32) {
            float4 a = xi[q];
            float4 bq = xj[q];
            sxx += a.x * a.x + a.y * a.y + a.z * a.z + a.w * a.w;
            syy += bq.x * bq.x + bq.y * bq.y + bq.z * bq.z + bq.w * bq.w;
            sxy += a.x * bq.x + a.y * bq.y + a.z * bq.z + a.w * bq.w;
        }
#pragma unroll
        for (int o = 16; o; o >>= 1) {
            sxx += __shfl_xor_sync(0xFFFFFFFFu, sxx, o);
            syy += __shfl_xor_sync(0xFFFFFFFFu, syy, o);
            sxy += __shfl_xor_sync(0xFFFFFFFFu, sxy, o);
        }
        float ni = fmaxf(sqrtf(sxx), 1e-12f);
        float nj = fmaxf(sqrtf(syy), 1e-12f);
        float sc = (sxy / (ni * nj)) * 2.0f;         // / TEMPERATURE (0.5)
        float xs = (p < npos) ? -sc : sc;
        acc += fmaxf(xs, 0.f) + log1pf(expf(-fabsf(xs)));  // softplus(xs)
    }

    // acc replicated across lanes -> lane 0's copy IS the warp partial
    if (lane == 0) part[w] = acc;
    __syncthreads();
    if (w == 0) {
        float vv = part[lane];
#pragma unroll
        for (int o = 16; o; o >>= 1) vv += __shfl_xor_sync(0xFFFFFFFFu, vv, o);
        if (lane == 0) {
            g_part[b] = vv;
            __threadfence();
            g_flagL[b] = epoch;
        }
    }

    // ---- block 0 combines the NLOSS partials deterministically ----
    if (b == 0) {
        if (tid < NLOSS)
            while (g_flagL[tid] < epoch) { }
        __syncthreads();
        __threadfence();
        if (tid == 0) {
            float tot = 0.0f;
#pragma unroll
            for (int r = 0; r < NLOSS; r++) tot += g_part[r];
            out[0] = tot / (float)n;
        }
    }
}

extern "C" void kernel_launch(void* const* d_in, const int* in_sizes, int n_in,
                              void* d_out, int out_size) {
    const float* x = (const float*)d_in[0];   // identity_tokens [B, D] fp32
    const void* sids = d_in[1];               // subject_ids [B]
    int B = in_sizes[1];
    int D = in_sizes[0] / B;

    cudaFuncSetAttribute(fused_contrastive,
                         cudaFuncAttributeMaxDynamicSharedMemorySize, SMEM_TOTAL);

    fused_contrastive<<<GRID, T, SMEM_TOTAL>>>(sids, x, (float*)d_out, B, D);
}